// round 16
// baseline (speedup 1.0000x reference)
#include <cuda_runtime.h>
#include <math.h>
#include <stdint.h>

#define NOBJ  256
#define CCLS  151
#define DH    512
#define KFULL (CCLS*DH)
#define GLD   2048

#define OFF_BIGB 0
#define OFF_W5U  (2048*512)
#define OFF_WO   (OFF_W5U + 512*512)
#define OFF_WCS  (OFF_WO + 512*1024)
#define W_TOTAL  (OFF_WCS + 192*512)

enum { EPI_STORE=0, EPI_RELU=2, EPI_CLS=3 };
struct EpiArgs { const float* bias; };

// ---------------- device scratch (allocation-free) ---------------------------
__device__ uint32_t g_Wh[W_TOTAL];        // tf32 hi planes of all weights
__device__ uint32_t g_Wl[W_TOTAL];        // tf32 lo planes
__device__ float g_hA[NOBJ*1024];         // [h | input], ping
__device__ float g_hB[NOBJ*1024];         // [h | input], pong
__device__ float g_Gm[257*GLD];           // G rows 0-255, row 256 = tot@B^T
__device__ float g_on[NOBJ*DH];
__device__ float g_hp[8*DH];              // hsum partials (by 32-row block)

// ---------------- helpers -----------------------------------------------------
__device__ __forceinline__ uint32_t f2tf(float x) {
    uint32_t u; asm("cvt.rna.tf32.f32 %0, %1;" : "=r"(u) : "f"(x)); return u;
}
__device__ __forceinline__ void split4(float4 v, uint4& hi, uint4& lo) {
    hi = make_uint4(f2tf(v.x), f2tf(v.y), f2tf(v.z), f2tf(v.w));
    lo = make_uint4(f2tf(v.x - __uint_as_float(hi.x)),
                    f2tf(v.y - __uint_as_float(hi.y)),
                    f2tf(v.z - __uint_as_float(hi.z)),
                    f2tf(v.w - __uint_as_float(hi.w)));
}
__device__ __forceinline__ void cp16(uint32_t dst, const void* src) {
    asm volatile("cp.async.cg.shared.global [%0], [%1], 16;" :: "r"(dst), "l"(src));
}
__device__ __forceinline__ float sigf(float x) { return 1.f/(1.f + expf(-x)); }
__device__ __forceinline__ void mma8(float* c, const uint32_t* a, uint32_t b0, uint32_t b1) {
    asm volatile("mma.sync.aligned.m16n8k8.row.col.f32.tf32.tf32.f32 "
        "{%0,%1,%2,%3},{%4,%5,%6,%7},{%8,%9},{%0,%1,%2,%3};"
        : "+f"(c[0]), "+f"(c[1]), "+f"(c[2]), "+f"(c[3])
        : "r"(a[0]), "r"(a[1]), "r"(a[2]), "r"(a[3]), "r"(b0), "r"(b1));
}

// --------- setup: fold+split weights, init h buffers --------------------------
__global__ void k_setup(const float* __restrict__ inp,
                        const float* __restrict__ w3w, const float* __restrict__ w4w,
                        const float* __restrict__ w5w, const float* __restrict__ w3u,
                        const float* __restrict__ w5u, const float* __restrict__ wo) {
    int i = blockIdx.x*256 + threadIdx.x;            // float4 index, < 491520
    if (i < 262144) {
        int o = i >> 7, kq = i & 127;
        float4 v;
        if (o < 1536) {
            int q = o >> 9, oc = o & 511;
            const float4* w = (const float4*)((q==0) ? w3w : (q==1) ? w4w : w5w);
            float4 x = w[oc*256 + kq], y = w[oc*256 + 128 + kq];
            v = make_float4(x.x+y.x, x.y+y.y, x.z+y.z, x.w+y.w);
        } else {
            v = ((const float4*)w3u)[(o-1536)*128 + kq];
        }
        uint4 h, l; split4(v, h, l);
        ((uint4*)(g_Wh + OFF_BIGB))[i] = h;
        ((uint4*)(g_Wl + OFF_BIGB))[i] = l;
    } else if (i < 327680) {
        int j = i - 262144;
        uint4 h, l; split4(((const float4*)w5u)[j], h, l);
        ((uint4*)(g_Wh + OFF_W5U))[j] = h;
        ((uint4*)(g_Wl + OFF_W5U))[j] = l;
    } else if (i < 458752) {
        int j = i - 327680;
        uint4 h, l; split4(((const float4*)wo)[j], h, l);
        ((uint4*)(g_Wh + OFF_WO))[j] = h;
        ((uint4*)(g_Wl + OFF_WO))[j] = l;
    } else if (i < 491520) {
        int j = i - 458752;                          // < 32768
        int n = j >> 7, c4 = j & 127;
        float4 v = ((const float4*)inp)[j];
        ((float4*)g_hA)[n*256 + c4]       = v;       // h := input (ping)
        ((float4*)g_hA)[n*256 + 128 + c4] = v;       // input copy (ping)
        ((float4*)g_hB)[n*256 + 128 + c4] = v;       // input copy (pong)
    }
}

// --------- fused wcsum --------------------------------------------------------
__global__ void __launch_bounds__(1024)
k_wcs(const float* __restrict__ wc) {
    __shared__ float4 red[8][128];
    int o = blockIdx.x, t = threadIdx.x;
    int chunk = t >> 7, tc = t & 127;
    int c0 = chunk*19, nc = min(19, CCLS - c0);
    const float4* p = (const float4*)(wc + (size_t)o*KFULL + (size_t)c0*DH) + tc;
    float4 acc = make_float4(0.f,0.f,0.f,0.f);
    for (int c = 0; c < nc; c++) {
        float4 q = p[c*128];
        acc.x+=q.x; acc.y+=q.y; acc.z+=q.z; acc.w+=q.w;
    }
    red[chunk][tc] = acc;
    __syncthreads();
    if (t < 128) {
        float4 s = make_float4(0.f,0.f,0.f,0.f);
        #pragma unroll
        for (int k = 0; k < 8; k++) {
            float4 q = red[k][t];
            s.x+=q.x; s.y+=q.y; s.z+=q.z; s.w+=q.w;
        }
        uint4 h, l; split4(s, h, l);
        ((uint4*)(g_Wh + OFF_WCS + o*DH))[t] = h;
        ((uint4*)(g_Wl + OFF_WCS + o*DH))[t] = l;
    }
}

__global__ void k_hs() {                             // once, on initial h (ping)
    int d  = blockIdx.x*128 + threadIdx.x;
    int n0 = blockIdx.y*32;
    float s = 0.f;
    #pragma unroll
    for (int i = 0; i < 32; i++) s += g_hA[(n0+i)*1024 + d];
    g_hp[blockIdx.y*DH + d] = s;
}

// ------------- generic 3xTF32 GEMM, cp.async pipeline -------------------------
template<int SYNTH>
__device__ __forceinline__ float4 loadAx(const float* A, int lda, int arow, int kc) {
    if (SYNTH) {
        if (arow == 256) {                           // synthesize hsum row
            float4 s = make_float4(0.f,0.f,0.f,0.f);
            #pragma unroll
            for (int p = 0; p < 8; p++) {
                float4 q = *(const float4*)&g_hp[p*DH + kc];
                s.x+=q.x; s.y+=q.y; s.z+=q.z; s.w+=q.w;
            }
            return s;
        }
        if (arow > 256) return make_float4(0.f,0.f,0.f,0.f);
    }
    return *(const float4*)(A + (size_t)arow*lda + kc);
}

template<int EPI> __device__ __forceinline__
void epi_store(float v, int r, int c, float* C, int ldc, const EpiArgs& ea) {
    if (EPI == EPI_STORE) {
        C[(size_t)r*ldc + c] = v;
    } else if (EPI == EPI_RELU) {
        C[(size_t)r*ldc + c] = fmaxf(v + ea.bias[c], 0.f);
    } else { // EPI_CLS
        if (c < CCLS) C[(size_t)r*CCLS + c] = v + ea.bias[c];
    }
}

// BM=32, BN=BNT, 256 threads (8 warps 2x4), warp tile 16x(8*NI).
template<int EPI, int KD, int BNT, int SYNTH>
__global__ void __launch_bounds__(256)
k_gemm(const float* __restrict__ A, int lda,
       const uint32_t* __restrict__ Bh_g, const uint32_t* __restrict__ Bl_g, int ldb,
       float* __restrict__ C, int ldc, EpiArgs ea)
{
    constexpr int NI  = BNT/32;
    constexpr int STG = 2304 + 72*BNT;
    constexpr int KT  = KD/32;
    extern __shared__ uint32_t sm[];
    const int r0 = blockIdx.y*32, c0 = blockIdx.x*BNT;
    const int tid = threadIdx.x;
    const int lane = tid & 31, warp = tid >> 5;
    const int wm = warp & 1, wn = warp >> 1;
    const int group = lane >> 2, tg = lane & 3;
    const int lr = tid >> 3, lk = (tid & 7) << 2;
    const uint32_t smb = (uint32_t)__cvta_generic_to_shared(sm);

    float acc[3][NI][4];
    #pragma unroll
    for (int s = 0; s < 3; s++)
        #pragma unroll
        for (int ni = 0; ni < NI; ni++)
            #pragma unroll
            for (int q = 0; q < 4; q++) acc[s][ni][q] = 0.f;

    float4 ar = loadAx<SYNTH>(A, lda, r0 + lr, lk);
    {
        #pragma unroll
        for (int i = 0; i < NI; i++) {
            int row = lr + i*32;
            cp16(smb + 4*(2304 + row*36 + lk),          Bh_g + (size_t)(c0+row)*ldb + lk);
            cp16(smb + 4*(2304 + 36*BNT + row*36 + lk), Bl_g + (size_t)(c0+row)*ldb + lk);
        }
        asm volatile("cp.async.commit_group;" ::: "memory");
        uint4 h, l; split4(ar, h, l);
        *(uint4*)&sm[lr*36 + lk]        = h;
        *(uint4*)&sm[1152 + lr*36 + lk] = l;
        asm volatile("cp.async.wait_group 0;" ::: "memory");
    }
    __syncthreads();

    for (int kt = 0; kt < KT; kt++) {
        const int cs = (kt & 1)*STG;
        const uint32_t* AhS = sm + cs;
        const uint32_t* AlS = sm + cs + 1152;
        const uint32_t* BhS = sm + cs + 2304;
        const uint32_t* BlS = sm + cs + 2304 + 36*BNT;

        if (kt + 1 < KT) {
            const int ns = ((kt + 1) & 1)*STG;
            ar = loadAx<SYNTH>(A, lda, r0 + lr, (kt+1)*32 + lk);
            #pragma unroll
            for (int i = 0; i < NI; i++) {
                int row = lr + i*32;
                cp16(smb + 4*(ns + 2304 + row*36 + lk),
                     Bh_g + (size_t)(c0+row)*ldb + (kt+1)*32 + lk);
                cp16(smb + 4*(ns + 2304 + 36*BNT + row*36 + lk),
                     Bl_g + (size_t)(c0+row)*ldb + (kt+1)*32 + lk);
            }
            asm volatile("cp.async.commit_group;" ::: "memory");
        }

        #pragma unroll
        for (int kk = 0; kk < 32; kk += 8) {
            uint32_t ah[4], al[4];
            int row = wm*16 + group;
            ah[0] = AhS[ row     *36 + kk + tg];
            ah[1] = AhS[(row + 8)*36 + kk + tg];
            ah[2] = AhS[ row     *36 + kk + tg + 4];
            ah[3] = AhS[(row + 8)*36 + kk + tg + 4];
            al[0] = AlS[ row     *36 + kk + tg];
            al[1] = AlS[(row + 8)*36 + kk + tg];
            al[2] = AlS[ row     *36 + kk + tg + 4];
            al[3] = AlS[(row + 8)*36 + kk + tg + 4];
            #pragma unroll
            for (int ni = 0; ni < NI; ni++) {
                int col = wn*8*NI + ni*8 + group;
                uint32_t bh0 = BhS[col*36 + kk + tg], bh1 = BhS[col*36 + kk + tg + 4];
                uint32_t bl0 = BlS[col*36 + kk + tg], bl1 = BlS[col*36 + kk + tg + 4];
                mma8(acc[0][ni], ah, bl0, bl1);
                mma8(acc[1][ni], al, bh0, bh1);
                mma8(acc[2][ni], ah, bh0, bh1);
            }
        }

        if (kt + 1 < KT) {
            const int ns = ((kt + 1) & 1)*STG;
            uint4 h, l; split4(ar, h, l);
            *(uint4*)&sm[ns + lr*36 + lk]        = h;
            *(uint4*)&sm[ns + 1152 + lr*36 + lk] = l;
            asm volatile("cp.async.wait_group 0;" ::: "memory");
        }
        __syncthreads();
    }

    int r1 = r0 + wm*16 + group;
    #pragma unroll
    for (int ni = 0; ni < NI; ni++) {
        int cc = c0 + wn*8*NI + ni*8 + tg*2;
        #pragma unroll
        for (int q = 0; q < 4; q++) {
            float v = acc[0][ni][q] + acc[1][ni][q] + acc[2][ni][q];
            epi_store<EPI>(v, r1 + (q >> 1)*8, cc + (q & 1), C, ldc, ea);
        }
    }
}

// ------------- GRU GEMM: gates fused into A-path and epilogue -----------------
// A[n,d] = sigmoid(a4+U)*h_old[n,d] computed on the fly from g_Gm.
// Epilogue: h_new = (1-z)h_old + z*tanh(V + b5u + a5), + column partials -> g_hp.
__global__ void __launch_bounds__(256)
k_grux(const float* __restrict__ hold, float* __restrict__ hnew,
       const float* __restrict__ matrix,
       const float* __restrict__ b3w, const float* __restrict__ b4w,
       const float* __restrict__ b5w, const float* __restrict__ b3u,
       const float* __restrict__ b5u,
       const uint32_t* __restrict__ Bh_g, const uint32_t* __restrict__ Bl_g)
{
    constexpr int STG = 4608, KT = 16;               // BNT=32
    extern __shared__ uint32_t sm[];
    const int r0 = blockIdx.y*32, c0 = blockIdx.x*32;
    const int tid = threadIdx.x;
    const int lane = tid & 31, warp = tid >> 5;
    const int wm = warp & 1, wn = warp >> 1;
    const int group = lane >> 2, tg = lane & 3;
    const int lr = tid >> 3, lk = (tid & 7) << 2;
    const int n = r0 + lr;
    const uint32_t smb = (uint32_t)__cvta_generic_to_shared(sm);
    const float sc = matrix[0] * (float)CCLS;

    float acc[3][4];
    #pragma unroll
    for (int s = 0; s < 3; s++)
        #pragma unroll
        for (int q = 0; q < 4; q++) acc[s][q] = 0.f;

    float4 g15, g5, t5, bu, bw, hh;
    #define FETCH_A(kc) do { \
        g15 = *(const float4*)&g_Gm[(size_t)n*GLD + 1536 + (kc)]; \
        g5  = *(const float4*)&g_Gm[(size_t)n*GLD + 512  + (kc)]; \
        t5  = *(const float4*)&g_Gm[(size_t)256*GLD + 512 + (kc)]; \
        bu  = *(const float4*)(b3u + (kc)); \
        bw  = *(const float4*)(b4w + (kc)); \
        hh  = *(const float4*)(hold + (size_t)n*1024 + (kc)); \
    } while (0)
    #define STORE_A(st) do { \
        float4 rh; \
        rh.x = sigf(sc*(t5.x-g5.x)+bw.x + g15.x+bu.x) * hh.x; \
        rh.y = sigf(sc*(t5.y-g5.y)+bw.y + g15.y+bu.y) * hh.y; \
        rh.z = sigf(sc*(t5.z-g5.z)+bw.z + g15.z+bu.z) * hh.z; \
        rh.w = sigf(sc*(t5.w-g5.w)+bw.w + g15.w+bu.w) * hh.w; \
        uint4 h_, l_; split4(rh, h_, l_); \
        *(uint4*)&sm[(st) + lr*36 + lk]        = h_; \
        *(uint4*)&sm[(st) + 1152 + lr*36 + lk] = l_; \
    } while (0)

    FETCH_A(lk);
    {
        cp16(smb + 4*(2304 + lr*36 + lk),        Bh_g + (size_t)(c0+lr)*DH + lk);
        cp16(smb + 4*(2304 + 1152 + lr*36 + lk), Bl_g + (size_t)(c0+lr)*DH + lk);
        asm volatile("cp.async.commit_group;" ::: "memory");
        STORE_A(0);
        asm volatile("cp.async.wait_group 0;" ::: "memory");
    }
    __syncthreads();

    for (int kt = 0; kt < KT; kt++) {
        const int cs = (kt & 1)*STG;
        const uint32_t* AhS = sm + cs;
        const uint32_t* AlS = sm + cs + 1152;
        const uint32_t* BhS = sm + cs + 2304;
        const uint32_t* BlS = sm + cs + 2304 + 1152;

        if (kt + 1 < KT) {
            const int ns = ((kt + 1) & 1)*STG;
            FETCH_A((kt+1)*32 + lk);
            cp16(smb + 4*(ns + 2304 + lr*36 + lk),
                 Bh_g + (size_t)(c0+lr)*DH + (kt+1)*32 + lk);
            cp16(smb + 4*(ns + 2304 + 1152 + lr*36 + lk),
                 Bl_g + (size_t)(c0+lr)*DH + (kt+1)*32 + lk);
            asm volatile("cp.async.commit_group;" ::: "memory");
        }

        #pragma unroll
        for (int kk = 0; kk < 32; kk += 8) {
            uint32_t ah[4], al[4];
            int row = wm*16 + group;
            ah[0] = AhS[ row     *36 + kk + tg];
            ah[1] = AhS[(row + 8)*36 + kk + tg];
            ah[2] = AhS[ row     *36 + kk + tg + 4];
            ah[3] = AhS[(row + 8)*36 + kk + tg + 4];
            al[0] = AlS[ row     *36 + kk + tg];
            al[1] = AlS[(row + 8)*36 + kk + tg];
            al[2] = AlS[ row     *36 + kk + tg + 4];
            al[3] = AlS[(row + 8)*36 + kk + tg + 4];
            int col = wn*8 + group;
            uint32_t bh0 = BhS[col*36 + kk + tg], bh1 = BhS[col*36 + kk + tg + 4];
            uint32_t bl0 = BlS[col*36 + kk + tg], bl1 = BlS[col*36 + kk + tg + 4];
            mma8(acc[0], ah, bl0, bl1);
            mma8(acc[1], al, bh0, bh1);
            mma8(acc[2], ah, bh0, bh1);
        }

        if (kt + 1 < KT) {
            const int ns = ((kt + 1) & 1)*STG;
            STORE_A(ns);
            asm volatile("cp.async.wait_group 0;" ::: "memory");
        }
        __syncthreads();
    }

    // epilogue: gates at output coords + h update + deterministic column partials
    float* red = (float*)(sm + 2*STG);               // [32][33]
    int r1 = r0 + wm*16 + group;
    #pragma unroll
    for (int q = 0; q < 4; q++) {
        float v  = acc[0][q] + acc[1][q] + acc[2][q];
        int rr = r1 + (q >> 1)*8;
        int cc = c0 + wn*8 + tg*2 + (q & 1);
        float U  = g_Gm[(size_t)rr*GLD + 1536 + cc] + b3u[cc];
        float a3 = sc*(g_Gm[(size_t)256*GLD + cc]        - g_Gm[(size_t)rr*GLD + cc])        + b3w[cc];
        float a5 = sc*(g_Gm[(size_t)256*GLD + 1024 + cc] - g_Gm[(size_t)rr*GLD + 1024 + cc]) + b5w[cc];
        float z  = sigf(a3 + U);
        float hv = tanhf(v + b5u[cc] + a5);
        float nh = (1.f - z)*hold[(size_t)rr*1024 + cc] + z*hv;
        hnew[(size_t)rr*1024 + cc] = nh;
        int lrow = wm*16 + group + (q >> 1)*8;
        int lcol = wn*8 + tg*2 + (q & 1);
        red[lrow*33 + lcol] = nh;
    }
    __syncthreads();
    if (tid < 32) {
        float s = 0.f;
        #pragma unroll
        for (int rws = 0; rws < 32; rws++) s += red[rws*33 + tid];
        g_hp[blockIdx.y*DH + c0 + tid] = s;
    }
    #undef FETCH_A
    #undef STORE_A
}

// ---------------- host ------------------------------------------------------
extern "C" void kernel_launch(void* const* d_in, const int* in_sizes, int n_in,
                              void* d_out, int out_size)
{
    const float* input  = (const float*)d_in[0];
    const float* matrix = (const float*)d_in[1];
    const float* w3w = (const float*)d_in[2];  const float* b3w = (const float*)d_in[3];
    const float* w3u = (const float*)d_in[4];  const float* b3u = (const float*)d_in[5];
    const float* w4w = (const float*)d_in[6];  const float* b4w = (const float*)d_in[7];
    /* w4u, b4u unused: reference reuses w3u/b3u */
    const float* w5w = (const float*)d_in[10]; const float* b5w = (const float*)d_in[11];
    const float* w5u = (const float*)d_in[12]; const float* b5u = (const float*)d_in[13];
    const float* wo  = (const float*)d_in[14]; const float* bo  = (const float*)d_in[15];
    const float* wc  = (const float*)d_in[16]; const float* bc  = (const float*)d_in[17];
    float* out = (float*)d_out;

    float *phA, *phB, *pG, *pon;
    uint32_t *pWh, *pWl;
    cudaGetSymbolAddress((void**)&pWh, g_Wh);
    cudaGetSymbolAddress((void**)&pWl, g_Wl);
    cudaGetSymbolAddress((void**)&phA, g_hA);
    cudaGetSymbolAddress((void**)&phB, g_hB);
    cudaGetSymbolAddress((void**)&pG,  g_Gm);
    cudaGetSymbolAddress((void**)&pon, g_on);

    const int SM_BIG = (2304 + 72*64)*2*4;           // 55296 B
    const int SM_SML = (2304 + 72*32)*2*4;           // 36864 B
    const int SM_GRU = SM_SML + 32*33*4;             // 41088 B
    cudaFuncSetAttribute(k_gemm<EPI_STORE,512,64,1>,
                         cudaFuncAttributeMaxDynamicSharedMemorySize, SM_BIG);

    EpiArgs e0 = {nullptr};

    k_setup<<<1920, 256>>>(input, w3w, w4w, w5w, w3u, w5u, wo);
    k_wcs  <<<CCLS, 1024>>>(wc);
    k_hs   <<<dim3(4,8), 128>>>();

    float* hbuf[2] = {phA, phB};
    for (int t = 0; t < 3; t++) {
        float* hold = hbuf[t & 1];
        float* hnew = hbuf[(t + 1) & 1];
        // G rows 0..255 = h@B^T, row 256 = tot@B^T (A row 256 synthesized from g_hp)
        k_gemm<EPI_STORE,512,64,1><<<dim3(32,9), 256, SM_BIG>>>(
            hold, 1024, pWh+OFF_BIGB, pWl+OFF_BIGB, DH, pG, GLD, e0);
        // fused gates + (r*h)@w5u.T + GRU update + hsum partials
        k_grux<<<dim3(16,8), 256, SM_GRU>>>(
            hold, hnew, matrix, b3w, b4w, b5w, b3u, b5u,
            pWh+OFF_W5U, pWl+OFF_W5U);
    }

    // final h is in g_hB after 3 iterations
    EpiArgs er = {bo};
    k_gemm<EPI_RELU,1024,32,0><<<dim3(16,8), 256, SM_SML>>>(
        phB, 1024, pWh+OFF_WO, pWl+OFF_WO, 1024, pon, DH, er);
    EpiArgs ec = {bc};
    k_gemm<EPI_CLS,512,32,0><<<dim3(6,8), 256, SM_SML>>>(
        pon, DH, pWh+OFF_WCS, pWl+OFF_WCS, DH, out, CCLS, ec);
}

// round 17
// speedup vs baseline: 1.0351x; 1.0351x over previous
#include <cuda_runtime.h>
#include <math.h>
#include <stdint.h>

#define NOBJ  256
#define CCLS  151
#define DH    512
#define KFULL (CCLS*DH)
#define GLD   2048

#define OFF_BIGB 0
#define OFF_W5U  (2048*512)
#define OFF_WO   (OFF_W5U + 512*512)
#define OFF_WCS  (OFF_WO + 512*1024)
#define W_TOTAL  (OFF_WCS + 192*512)

enum { EPI_STORE=0, EPI_RELU=2, EPI_CLS=3 };
struct EpiArgs { const float* bias; };

// ---------------- device scratch (allocation-free) ---------------------------
__device__ uint32_t g_Wh[W_TOTAL];        // tf32 hi planes of all weights
__device__ uint32_t g_Wl[W_TOTAL];        // tf32 lo planes
__device__ float g_hA[NOBJ*1024];         // [h | input], ping
__device__ float g_hB[NOBJ*1024];         // [h | input], pong
__device__ float g_Gm[257*GLD];           // G rows 0-255, row 256 = tot@B^T
__device__ float g_on[NOBJ*DH];
__device__ float g_hp[8*DH];              // hsum partials (by 32-row block)

// ---------------- helpers -----------------------------------------------------
__device__ __forceinline__ uint32_t f2tf(float x) {
    uint32_t u; asm("cvt.rna.tf32.f32 %0, %1;" : "=r"(u) : "f"(x)); return u;
}
__device__ __forceinline__ void split4(float4 v, uint4& hi, uint4& lo) {
    hi = make_uint4(f2tf(v.x), f2tf(v.y), f2tf(v.z), f2tf(v.w));
    lo = make_uint4(f2tf(v.x - __uint_as_float(hi.x)),
                    f2tf(v.y - __uint_as_float(hi.y)),
                    f2tf(v.z - __uint_as_float(hi.z)),
                    f2tf(v.w - __uint_as_float(hi.w)));
}
__device__ __forceinline__ void cp16(uint32_t dst, const void* src) {
    asm volatile("cp.async.cg.shared.global [%0], [%1], 16;" :: "r"(dst), "l"(src));
}
__device__ __forceinline__ float sigf(float x) { return 1.f/(1.f + expf(-x)); }
__device__ __forceinline__ void mma8(float* c, const uint32_t* a, uint32_t b0, uint32_t b1) {
    asm volatile("mma.sync.aligned.m16n8k8.row.col.f32.tf32.tf32.f32 "
        "{%0,%1,%2,%3},{%4,%5,%6,%7},{%8,%9},{%0,%1,%2,%3};"
        : "+f"(c[0]), "+f"(c[1]), "+f"(c[2]), "+f"(c[3])
        : "r"(a[0]), "r"(a[1]), "r"(a[2]), "r"(a[3]), "r"(b0), "r"(b1));
}

// --------- setup: fold+split weights, init h buffers --------------------------
__global__ void k_setup(const float* __restrict__ inp,
                        const float* __restrict__ w3w, const float* __restrict__ w4w,
                        const float* __restrict__ w5w, const float* __restrict__ w3u,
                        const float* __restrict__ w5u, const float* __restrict__ wo) {
    int i = blockIdx.x*256 + threadIdx.x;            // float4 index, < 491520
    if (i < 262144) {
        int o = i >> 7, kq = i & 127;
        float4 v;
        if (o < 1536) {
            int q = o >> 9, oc = o & 511;
            const float4* w = (const float4*)((q==0) ? w3w : (q==1) ? w4w : w5w);
            float4 x = w[oc*256 + kq], y = w[oc*256 + 128 + kq];
            v = make_float4(x.x+y.x, x.y+y.y, x.z+y.z, x.w+y.w);
        } else {
            v = ((const float4*)w3u)[(o-1536)*128 + kq];
        }
        uint4 h, l; split4(v, h, l);
        ((uint4*)(g_Wh + OFF_BIGB))[i] = h;
        ((uint4*)(g_Wl + OFF_BIGB))[i] = l;
    } else if (i < 327680) {
        int j = i - 262144;
        uint4 h, l; split4(((const float4*)w5u)[j], h, l);
        ((uint4*)(g_Wh + OFF_W5U))[j] = h;
        ((uint4*)(g_Wl + OFF_W5U))[j] = l;
    } else if (i < 458752) {
        int j = i - 327680;
        uint4 h, l; split4(((const float4*)wo)[j], h, l);
        ((uint4*)(g_Wh + OFF_WO))[j] = h;
        ((uint4*)(g_Wl + OFF_WO))[j] = l;
    } else if (i < 491520) {
        int j = i - 458752;                          // < 32768
        int n = j >> 7, c4 = j & 127;
        float4 v = ((const float4*)inp)[j];
        ((float4*)g_hA)[n*256 + c4]       = v;       // h := input (ping)
        ((float4*)g_hA)[n*256 + 128 + c4] = v;       // input copy (ping)
        ((float4*)g_hB)[n*256 + 128 + c4] = v;       // input copy (pong)
    }
}

// --------- fused wcsum --------------------------------------------------------
__global__ void __launch_bounds__(1024)
k_wcs(const float* __restrict__ wc) {
    __shared__ float4 red[8][128];
    int o = blockIdx.x, t = threadIdx.x;
    int chunk = t >> 7, tc = t & 127;
    int c0 = chunk*19, nc = min(19, CCLS - c0);
    const float4* p = (const float4*)(wc + (size_t)o*KFULL + (size_t)c0*DH) + tc;
    float4 acc = make_float4(0.f,0.f,0.f,0.f);
    for (int c = 0; c < nc; c++) {
        float4 q = p[c*128];
        acc.x+=q.x; acc.y+=q.y; acc.z+=q.z; acc.w+=q.w;
    }
    red[chunk][tc] = acc;
    __syncthreads();
    if (t < 128) {
        float4 s = make_float4(0.f,0.f,0.f,0.f);
        #pragma unroll
        for (int k = 0; k < 8; k++) {
            float4 q = red[k][t];
            s.x+=q.x; s.y+=q.y; s.z+=q.z; s.w+=q.w;
        }
        uint4 h, l; split4(s, h, l);
        ((uint4*)(g_Wh + OFF_WCS + o*DH))[t] = h;
        ((uint4*)(g_Wl + OFF_WCS + o*DH))[t] = l;
    }
}

__global__ void k_hs() {                             // once, on initial h (ping)
    int d  = blockIdx.x*128 + threadIdx.x;
    int n0 = blockIdx.y*32;
    float s = 0.f;
    #pragma unroll
    for (int i = 0; i < 32; i++) s += g_hA[(n0+i)*1024 + d];
    g_hp[blockIdx.y*DH + d] = s;
}

// ------------- generic 3xTF32 GEMM, cp.async pipeline -------------------------
// SYNTH row-256 fetch: uniform per-block slow path (only blocks with r0==256).
__device__ __forceinline__ float4 synth_row(int lr, int kc) {
    if (lr != 0) return make_float4(0.f,0.f,0.f,0.f);
    float4 s = make_float4(0.f,0.f,0.f,0.f);
    #pragma unroll
    for (int p = 0; p < 8; p++) {
        float4 q = *(const float4*)&g_hp[p*DH + kc];
        s.x+=q.x; s.y+=q.y; s.z+=q.z; s.w+=q.w;
    }
    return s;
}

template<int EPI> __device__ __forceinline__
void epi_store(float v, int r, int c, float* C, int ldc, const EpiArgs& ea) {
    if (EPI == EPI_STORE) {
        C[(size_t)r*ldc + c] = v;
    } else if (EPI == EPI_RELU) {
        C[(size_t)r*ldc + c] = fmaxf(v + ea.bias[c], 0.f);
    } else { // EPI_CLS
        if (c < CCLS) C[(size_t)r*CCLS + c] = v + ea.bias[c];
    }
}

// BM=32, BN=BNT, 256 threads (8 warps 2x4), warp tile 16x(8*NI).
template<int EPI, int KD, int BNT, int SYNTH>
__global__ void __launch_bounds__(256)
k_gemm(const float* __restrict__ A, int lda,
       const uint32_t* __restrict__ Bh_g, const uint32_t* __restrict__ Bl_g, int ldb,
       float* __restrict__ C, int ldc, EpiArgs ea)
{
    constexpr int NI  = BNT/32;
    constexpr int STG = 2304 + 72*BNT;
    constexpr int KT  = KD/32;
    extern __shared__ uint32_t sm[];
    const int r0 = blockIdx.y*32, c0 = blockIdx.x*BNT;
    const int tid = threadIdx.x;
    const int lane = tid & 31, warp = tid >> 5;
    const int wm = warp & 1, wn = warp >> 1;
    const int group = lane >> 2, tg = lane & 3;
    const int lr = tid >> 3, lk = (tid & 7) << 2;
    const uint32_t smb = (uint32_t)__cvta_generic_to_shared(sm);
    const bool synth_blk = SYNTH && (r0 == 256);     // block-uniform

    float acc[3][NI][4];
    #pragma unroll
    for (int s = 0; s < 3; s++)
        #pragma unroll
        for (int ni = 0; ni < NI; ni++)
            #pragma unroll
            for (int q = 0; q < 4; q++) acc[s][ni][q] = 0.f;

    float4 ar;
    if (synth_blk) ar = synth_row(lr, lk);
    else           ar = *(const float4*)(A + (size_t)(r0 + lr)*lda + lk);
    {
        #pragma unroll
        for (int i = 0; i < NI; i++) {
            int row = lr + i*32;
            cp16(smb + 4*(2304 + row*36 + lk),          Bh_g + (size_t)(c0+row)*ldb + lk);
            cp16(smb + 4*(2304 + 36*BNT + row*36 + lk), Bl_g + (size_t)(c0+row)*ldb + lk);
        }
        asm volatile("cp.async.commit_group;" ::: "memory");
        uint4 h, l; split4(ar, h, l);
        *(uint4*)&sm[lr*36 + lk]        = h;
        *(uint4*)&sm[1152 + lr*36 + lk] = l;
        asm volatile("cp.async.wait_group 0;" ::: "memory");
    }
    __syncthreads();

    for (int kt = 0; kt < KT; kt++) {
        const int cs = (kt & 1)*STG;
        const uint32_t* AhS = sm + cs;
        const uint32_t* AlS = sm + cs + 1152;
        const uint32_t* BhS = sm + cs + 2304;
        const uint32_t* BlS = sm + cs + 2304 + 36*BNT;

        if (kt + 1 < KT) {
            const int ns = ((kt + 1) & 1)*STG;
            if (synth_blk) ar = synth_row(lr, (kt+1)*32 + lk);
            else           ar = *(const float4*)(A + (size_t)(r0 + lr)*lda + (kt+1)*32 + lk);
            #pragma unroll
            for (int i = 0; i < NI; i++) {
                int row = lr + i*32;
                cp16(smb + 4*(ns + 2304 + row*36 + lk),
                     Bh_g + (size_t)(c0+row)*ldb + (kt+1)*32 + lk);
                cp16(smb + 4*(ns + 2304 + 36*BNT + row*36 + lk),
                     Bl_g + (size_t)(c0+row)*ldb + (kt+1)*32 + lk);
            }
            asm volatile("cp.async.commit_group;" ::: "memory");
        }

        #pragma unroll
        for (int kk = 0; kk < 32; kk += 8) {
            uint32_t ah[4], al[4];
            int row = wm*16 + group;
            ah[0] = AhS[ row     *36 + kk + tg];
            ah[1] = AhS[(row + 8)*36 + kk + tg];
            ah[2] = AhS[ row     *36 + kk + tg + 4];
            ah[3] = AhS[(row + 8)*36 + kk + tg + 4];
            al[0] = AlS[ row     *36 + kk + tg];
            al[1] = AlS[(row + 8)*36 + kk + tg];
            al[2] = AlS[ row     *36 + kk + tg + 4];
            al[3] = AlS[(row + 8)*36 + kk + tg + 4];
            #pragma unroll
            for (int ni = 0; ni < NI; ni++) {
                int col = wn*8*NI + ni*8 + group;
                uint32_t bh0 = BhS[col*36 + kk + tg], bh1 = BhS[col*36 + kk + tg + 4];
                uint32_t bl0 = BlS[col*36 + kk + tg], bl1 = BlS[col*36 + kk + tg + 4];
                mma8(acc[0][ni], ah, bl0, bl1);
                mma8(acc[1][ni], al, bh0, bh1);
                mma8(acc[2][ni], ah, bh0, bh1);
            }
        }

        if (kt + 1 < KT) {
            const int ns = ((kt + 1) & 1)*STG;
            uint4 h, l; split4(ar, h, l);
            *(uint4*)&sm[ns + lr*36 + lk]        = h;
            *(uint4*)&sm[ns + 1152 + lr*36 + lk] = l;
            asm volatile("cp.async.wait_group 0;" ::: "memory");
        }
        __syncthreads();
    }

    int r1 = r0 + wm*16 + group;
    #pragma unroll
    for (int ni = 0; ni < NI; ni++) {
        int cc = c0 + wn*8*NI + ni*8 + tg*2;
        #pragma unroll
        for (int q = 0; q < 4; q++) {
            float v = acc[0][ni][q] + acc[1][ni][q] + acc[2][ni][q];
            epi_store<EPI>(v, r1 + (q >> 1)*8, cc + (q & 1), C, ldc, ea);
        }
    }
}

// ------------- GRU GEMM: gates fused into A-path and epilogue -----------------
__global__ void __launch_bounds__(256)
k_grux(const float* __restrict__ hold, float* __restrict__ hnew,
       const float* __restrict__ matrix,
       const float* __restrict__ b3w, const float* __restrict__ b4w,
       const float* __restrict__ b5w, const float* __restrict__ b3u,
       const float* __restrict__ b5u,
       const uint32_t* __restrict__ Bh_g, const uint32_t* __restrict__ Bl_g)
{
    constexpr int STG = 4608, KT = 16;               // BNT=32
    extern __shared__ uint32_t sm[];
    const int r0 = blockIdx.y*32, c0 = blockIdx.x*32;
    const int tid = threadIdx.x;
    const int lane = tid & 31, warp = tid >> 5;
    const int wm = warp & 1, wn = warp >> 1;
    const int group = lane >> 2, tg = lane & 3;
    const int lr = tid >> 3, lk = (tid & 7) << 2;
    const int n = r0 + lr;
    const uint32_t smb = (uint32_t)__cvta_generic_to_shared(sm);
    const float sc = matrix[0] * (float)CCLS;

    float acc[3][4];
    #pragma unroll
    for (int s = 0; s < 3; s++)
        #pragma unroll
        for (int q = 0; q < 4; q++) acc[s][q] = 0.f;

    float4 g15, g5, t5, bu, bw, hh;
    #define FETCH_A(kc) do { \
        g15 = *(const float4*)&g_Gm[(size_t)n*GLD + 1536 + (kc)]; \
        g5  = *(const float4*)&g_Gm[(size_t)n*GLD + 512  + (kc)]; \
        t5  = *(const float4*)&g_Gm[(size_t)256*GLD + 512 + (kc)]; \
        bu  = *(const float4*)(b3u + (kc)); \
        bw  = *(const float4*)(b4w + (kc)); \
        hh  = *(const float4*)(hold + (size_t)n*1024 + (kc)); \
    } while (0)
    #define STORE_A(st) do { \
        float4 rh; \
        rh.x = sigf(sc*(t5.x-g5.x)+bw.x + g15.x+bu.x) * hh.x; \
        rh.y = sigf(sc*(t5.y-g5.y)+bw.y + g15.y+bu.y) * hh.y; \
        rh.z = sigf(sc*(t5.z-g5.z)+bw.z + g15.z+bu.z) * hh.z; \
        rh.w = sigf(sc*(t5.w-g5.w)+bw.w + g15.w+bu.w) * hh.w; \
        uint4 h_, l_; split4(rh, h_, l_); \
        *(uint4*)&sm[(st) + lr*36 + lk]        = h_; \
        *(uint4*)&sm[(st) + 1152 + lr*36 + lk] = l_; \
    } while (0)

    FETCH_A(lk);
    {
        cp16(smb + 4*(2304 + lr*36 + lk),        Bh_g + (size_t)(c0+lr)*DH + lk);
        cp16(smb + 4*(2304 + 1152 + lr*36 + lk), Bl_g + (size_t)(c0+lr)*DH + lk);
        asm volatile("cp.async.commit_group;" ::: "memory");
        STORE_A(0);
        asm volatile("cp.async.wait_group 0;" ::: "memory");
    }
    __syncthreads();

    for (int kt = 0; kt < KT; kt++) {
        const int cs = (kt & 1)*STG;
        const uint32_t* AhS = sm + cs;
        const uint32_t* AlS = sm + cs + 1152;
        const uint32_t* BhS = sm + cs + 2304;
        const uint32_t* BlS = sm + cs + 2304 + 1152;

        if (kt + 1 < KT) {
            const int ns = ((kt + 1) & 1)*STG;
            FETCH_A((kt+1)*32 + lk);
            cp16(smb + 4*(ns + 2304 + lr*36 + lk),
                 Bh_g + (size_t)(c0+lr)*DH + (kt+1)*32 + lk);
            cp16(smb + 4*(ns + 2304 + 1152 + lr*36 + lk),
                 Bl_g + (size_t)(c0+lr)*DH + (kt+1)*32 + lk);
            asm volatile("cp.async.commit_group;" ::: "memory");
        }

        #pragma unroll
        for (int kk = 0; kk < 32; kk += 8) {
            uint32_t ah[4], al[4];
            int row = wm*16 + group;
            ah[0] = AhS[ row     *36 + kk + tg];
            ah[1] = AhS[(row + 8)*36 + kk + tg];
            ah[2] = AhS[ row     *36 + kk + tg + 4];
            ah[3] = AhS[(row + 8)*36 + kk + tg + 4];
            al[0] = AlS[ row     *36 + kk + tg];
            al[1] = AlS[(row + 8)*36 + kk + tg];
            al[2] = AlS[ row     *36 + kk + tg + 4];
            al[3] = AlS[(row + 8)*36 + kk + tg + 4];
            int col = wn*8 + group;
            uint32_t bh0 = BhS[col*36 + kk + tg], bh1 = BhS[col*36 + kk + tg + 4];
            uint32_t bl0 = BlS[col*36 + kk + tg], bl1 = BlS[col*36 + kk + tg + 4];
            mma8(acc[0], ah, bl0, bl1);
            mma8(acc[1], al, bh0, bh1);
            mma8(acc[2], ah, bh0, bh1);
        }

        if (kt + 1 < KT) {
            const int ns = ((kt + 1) & 1)*STG;
            STORE_A(ns);
            asm volatile("cp.async.wait_group 0;" ::: "memory");
        }
        __syncthreads();
    }

    // epilogue: gates at output coords + h update + deterministic column partials
    float* red = (float*)(sm + 2*STG);               // [32][33]
    int r1 = r0 + wm*16 + group;
    #pragma unroll
    for (int q = 0; q < 4; q++) {
        float v  = acc[0][q] + acc[1][q] + acc[2][q];
        int rr = r1 + (q >> 1)*8;
        int cc = c0 + wn*8 + tg*2 + (q & 1);
        float U  = g_Gm[(size_t)rr*GLD + 1536 + cc] + b3u[cc];
        float a3 = sc*(g_Gm[(size_t)256*GLD + cc]        - g_Gm[(size_t)rr*GLD + cc])        + b3w[cc];
        float a5 = sc*(g_Gm[(size_t)256*GLD + 1024 + cc] - g_Gm[(size_t)rr*GLD + 1024 + cc]) + b5w[cc];
        float z  = sigf(a3 + U);
        float hv = tanhf(v + b5u[cc] + a5);
        float nh = (1.f - z)*hold[(size_t)rr*1024 + cc] + z*hv;
        hnew[(size_t)rr*1024 + cc] = nh;
        int lrow = wm*16 + group + (q >> 1)*8;
        int lcol = wn*8 + tg*2 + (q & 1);
        red[lrow*33 + lcol] = nh;
    }
    __syncthreads();
    if (tid < 32) {
        float s = 0.f;
        #pragma unroll
        for (int rws = 0; rws < 32; rws++) s += red[rws*33 + tid];
        g_hp[blockIdx.y*DH + c0 + tid] = s;
    }
    #undef FETCH_A
    #undef STORE_A
}

// ---------------- host ------------------------------------------------------
extern "C" void kernel_launch(void* const* d_in, const int* in_sizes, int n_in,
                              void* d_out, int out_size)
{
    const float* input  = (const float*)d_in[0];
    const float* matrix = (const float*)d_in[1];
    const float* w3w = (const float*)d_in[2];  const float* b3w = (const float*)d_in[3];
    const float* w3u = (const float*)d_in[4];  const float* b3u = (const float*)d_in[5];
    const float* w4w = (const float*)d_in[6];  const float* b4w = (const float*)d_in[7];
    /* w4u, b4u unused: reference reuses w3u/b3u */
    const float* w5w = (const float*)d_in[10]; const float* b5w = (const float*)d_in[11];
    const float* w5u = (const float*)d_in[12]; const float* b5u = (const float*)d_in[13];
    const float* wo  = (const float*)d_in[14]; const float* bo  = (const float*)d_in[15];
    const float* wc  = (const float*)d_in[16]; const float* bc  = (const float*)d_in[17];
    float* out = (float*)d_out;

    float *phA, *phB, *pG, *pon;
    uint32_t *pWh, *pWl;
    cudaGetSymbolAddress((void**)&pWh, g_Wh);
    cudaGetSymbolAddress((void**)&pWl, g_Wl);
    cudaGetSymbolAddress((void**)&phA, g_hA);
    cudaGetSymbolAddress((void**)&phB, g_hB);
    cudaGetSymbolAddress((void**)&pG,  g_Gm);
    cudaGetSymbolAddress((void**)&pon, g_on);

    const int SM_BIG = (2304 + 72*64)*2*4;           // 55296 B
    const int SM_SML = (2304 + 72*32)*2*4;           // 36864 B
    const int SM_GRU = SM_SML + 32*33*4;             // 41088 B
    cudaFuncSetAttribute(k_gemm<EPI_STORE,512,64,1>,
                         cudaFuncAttributeMaxDynamicSharedMemorySize, SM_BIG);

    EpiArgs e0 = {nullptr};

    k_setup<<<1920, 256>>>(input, w3w, w4w, w5w, w3u, w5u, wo);
    k_wcs  <<<CCLS, 1024>>>(wc);
    k_hs   <<<dim3(4,8), 128>>>();

    float* hbuf[2] = {phA, phB};
    for (int t = 0; t < 3; t++) {
        float* hold = hbuf[t & 1];
        float* hnew = hbuf[(t + 1) & 1];
        // G rows 0..255 = h@B^T, row 256 = tot@B^T (row 256 synthesized, block-uniform)
        k_gemm<EPI_STORE,512,64,1><<<dim3(32,9), 256, SM_BIG>>>(
            hold, 1024, pWh+OFF_BIGB, pWl+OFF_BIGB, DH, pG, GLD, e0);
        // fused gates + (r*h)@w5u.T + GRU update + hsum partials
        k_grux<<<dim3(16,8), 256, SM_GRU>>>(
            hold, hnew, matrix, b3w, b4w, b5w, b3u, b5u,
            pWh+OFF_W5U, pWl+OFF_W5U);
    }

    // final h is in g_hB after 3 iterations
    EpiArgs er = {bo};
    k_gemm<EPI_RELU,1024,32,0><<<dim3(16,8), 256, SM_SML>>>(
        phB, 1024, pWh+OFF_WO, pWl+OFF_WO, 1024, pon, DH, er);
    EpiArgs ec = {bc};
    k_gemm<EPI_CLS,512,32,0><<<dim3(6,8), 256, SM_SML>>>(
        pon, DH, pWh+OFF_WCS, pWl+OFF_WCS, DH, out, CCLS, ec);
}